// round 14
// baseline (speedup 1.0000x reference)
#include <cuda_runtime.h>
#include <cuda_bf16.h>
#include <cstdint>

#define BB   8
#define LL   50
#define BL   400
#define MM   32
#define NHOP 2
#define DD   64
#define HH   2
#define HDD  32
#define RR   20
#define NBLK 2

// ---------------- scratch ----------------------------------------------------
__device__ float g_item [BL*DD];
__device__ float g_osum [BL*DD];
__device__ float g_V    [BL*RR*DD];
__device__ float g_x    [BL*DD];
__device__ float g_Q    [BL*DD];
__device__ float g_q    [BL*DD];
__device__ float g_k    [BL*DD];
__device__ float g_v    [BL*DD];
__device__ float g_q2   [BL*DD];
__device__ float g_k2   [BL*DD];
__device__ float g_v2   [BL*DD];

__device__ volatile int g_flagS[BB];
__device__ volatile int g_flagQ[BL];
__device__ volatile int g_flag2[BL];

__device__ __forceinline__ float lrelu(float x) { return x > 0.f ? x : 0.01f * x; }

// ---------------- V[bl,r,j] = sum_i item[bl,i] * R_r[i,j] --------------------
__global__ __launch_bounds__(256) void kv_rip(
    const float* __restrict__ rel, const float* __restrict__ E,
    const int* __restrict__ seq, int hop)
{
    __shared__ __align__(16) float IT[25*DD];
    const int u = blockIdx.x;
    const int r = u >> 4, c = u & 15;
    const int t = threadIdx.x;
    const int j = t & 63, gg = t >> 6;

    float Rj[64];
    const float* Rr = rel + (long)r*4096 + j;
    #pragma unroll
    for (int i = 0; i < 64; i++) Rj[i] = Rr[i*64];

    const int base = c * 25;
    for (int idx = t; idx < 25*DD; idx += 256) {
        int bl = base + (idx >> 6), d = idx & 63;
        IT[idx] = hop ? g_item[bl*DD + d] : E[(long)seq[bl]*DD + d];
    }
    __syncthreads();

    for (int l = gg; l < 25; l += 4) {
        const float4* it4 = (const float4*)(IT + l*DD);
        float a0 = 0.f, a1 = 0.f, a2 = 0.f, a3 = 0.f;
        #pragma unroll
        for (int k2 = 0; k2 < 4; k2++) {
            float4 x0 = it4[k2], x1 = it4[k2+4], x2 = it4[k2+8], x3 = it4[k2+12];
            a0 += x0.x*Rj[4*k2   ] + x0.y*Rj[4*k2+1 ] + x0.z*Rj[4*k2+2 ] + x0.w*Rj[4*k2+3 ];
            a1 += x1.x*Rj[4*k2+16] + x1.y*Rj[4*k2+17] + x1.z*Rj[4*k2+18] + x1.w*Rj[4*k2+19];
            a2 += x2.x*Rj[4*k2+32] + x2.y*Rj[4*k2+33] + x2.z*Rj[4*k2+34] + x2.w*Rj[4*k2+35];
            a3 += x3.x*Rj[4*k2+48] + x3.y*Rj[4*k2+49] + x3.z*Rj[4*k2+50] + x3.w*Rj[4*k2+51];
        }
        g_V[((long)(base + l)*RR + r)*DD + j] = (a0 + a1) + (a2 + a3);
    }
}

// ---------------- per-(b,l) hop update (256 threads) -------------------------
__global__ __launch_bounds__(256) void kh_rip(
    const float* __restrict__ E, const float* __restrict__ Wt,
    const int* __restrict__ mh, const int* __restrict__ mr, const int* __restrict__ mt,
    const int* __restrict__ seq, int hop, int last)
{
    __shared__ float sc[MM], pr[MM], u[DD], part[256], item_s[DD];
    const int bl = blockIdx.x, t = threadIdx.x;
    const int d = t & 63, quarter = t >> 6;
    const int mbase = (bl*NHOP + hop) * MM;

    // reset mega-kernel flags for this replay (runs strictly before mega)
    if (hop == 0 && t == 0) {
        g_flagQ[bl] = 0;
        g_flag2[bl] = 0;
        if (bl < BB) g_flagS[bl] = 0;
    }

    if (t < DD)
        item_s[t] = hop ? g_item[bl*DD + t] : E[(long)seq[bl]*DD + t];

    const int m = t >> 3, e8 = t & 7;
    const int hid = mh[mbase + m], rid = mr[mbase + m];
    const float4* Vv = (const float4*)(g_V + ((long)bl*RR + rid) * DD) + e8*2;
    const float4* Hh = (const float4*)(E + (long)hid * DD) + e8*2;
    float4 va0 = Vv[0], va1 = Vv[1], ha0 = Hh[0], ha1 = Hh[1];

    float treg[8];
    const int* mtb = mt + mbase + quarter*8;
    #pragma unroll
    for (int m2 = 0; m2 < 8; m2++)
        treg[m2] = E[(long)mtb[m2]*DD + d];

    float acc = va0.x*ha0.x + va0.y*ha0.y + va0.z*ha0.z + va0.w*ha0.w
              + va1.x*ha1.x + va1.y*ha1.y + va1.z*ha1.z + va1.w*ha1.w;
    acc += __shfl_down_sync(0xffffffffu, acc, 4, 8);
    acc += __shfl_down_sync(0xffffffffu, acc, 2, 8);
    acc += __shfl_down_sync(0xffffffffu, acc, 1, 8);
    if (e8 == 0) sc[m] = acc;
    __syncthreads();

    if (t < 32) {
        float v = sc[t];
        float mx = v;
        #pragma unroll
        for (int o = 16; o; o >>= 1) mx = fmaxf(mx, __shfl_xor_sync(0xffffffffu, mx, o));
        float e = __expf(v - mx);
        float s = e;
        #pragma unroll
        for (int o = 16; o; o >>= 1) s += __shfl_xor_sync(0xffffffffu, s, o);
        pr[t] = e / s;
    }
    __syncthreads();

    float od = 0.f;
    #pragma unroll
    for (int m2 = 0; m2 < 8; m2++)
        od += pr[quarter*8 + m2] * treg[m2];
    part[t] = od;
    __syncthreads();
    if (t < DD) {
        float o = part[t] + part[t + 64] + part[t + 128] + part[t + 192];
        if (hop == 0) g_osum[bl*DD + t] = o;
        else          g_osum[bl*DD + t] += o;
        u[t] = o + item_s[t];
    }
    __syncthreads();

    if (!last) {
        const float4* wr = (const float4*)(Wt + d*DD) + quarter*4;
        const float4* uu = (const float4*)u + quarter*4;
        float a = 0.f;
        #pragma unroll
        for (int kk = 0; kk < 4; kk++) {
            float4 w = wr[kk], x = uu[kk];
            a += w.x*x.x + w.y*x.y + w.z*x.z + w.w*x.w;
        }
        part[t] = a;
        __syncthreads();
        if (t < DD)
            g_item[bl*DD + t] = lrelu(part[t] + part[t+64] + part[t+128] + part[t+192]);
    }
}

// ---------------- mega: scan | qkv | kam0 | kam1 (forward-dep blocks) --------
struct ScanSM { float S[LL*DD]; float AB[128]; float T[128]; };
struct QkvSM  { float xs[DD]; float Qs[DD]; float mv[2]; };
struct KamSM  {
    float Kh[2][LL*36]; float Vh[2][LL*36];
    float qrow[DD]; float ps[2][52];
    float cs[DD]; float xr[DD]; float x2[DD]; float hdn[DD];
    float part[128]; float Qs[DD]; float mv[2];
};
union __align__(16) MegaSM { ScanSM scan; QkvSM qkv; KamSM kam; };

__global__ __launch_bounds__(128) void kmega_rip(
    const float* __restrict__ W1, const float* __restrict__ W2,
    const float* __restrict__ uemb, const int* __restrict__ user,
    const float* __restrict__ pemb, const float* __restrict__ E,
    const int* __restrict__ seq,
    const float* __restrict__ lnas, const float* __restrict__ lnab,
    const float* __restrict__ ipw,  const float* __restrict__ ipb,
    const float* __restrict__ opw,  const float* __restrict__ opb,
    const float* __restrict__ fs,   const float* __restrict__ fb,
    const float* __restrict__ c1w,  const float* __restrict__ c1b,
    const float* __restrict__ c2w,  const float* __restrict__ c2b,
    const float* __restrict__ lls,  const float* __restrict__ llb,
    const int* __restrict__ pos,    const int* __restrict__ neg,
    float* __restrict__ out)
{
    __shared__ MegaSM sm;
    const int blk = blockIdx.x, t = threadIdx.x;

    // =================== role: scan (blocks 0..7) ===================
    if (blk < BB) {
        const int b = blk;
        const int i = t & 63, path = t >> 6;
        float* S  = sm.scan.S;
        float* AB = sm.scan.AB;
        float* T  = sm.scan.T;

        const float* W = path ? W2 : W1;
        const float4* wr = (const float4*)(W + i*DD);
        float4 wv[16];
        #pragma unroll
        for (int kk = 0; kk < 16; kk++) wv[kk] = wr[kk];

        for (int idx = t; idx < LL*DD; idx += 128) {
            int l = idx >> 6, d = idx & 63;
            S[idx] = E[(long)seq[b*LL + l]*DD + d] + g_osum[b*LL*DD + idx];
        }
        float c = uemb[(long)user[b] * DD + i];
        __syncthreads();

        for (int st = 0; st < LL; st++) {
            float sv = S[st*DD + i];
            AB[path*64 + i] = path ? (sv * c) : (sv + c);
            __syncthreads();
            const float4* in = (const float4*)(AB + path*64);
            float a0 = 0.f, a1 = 0.f, a2 = 0.f, a3 = 0.f;
            #pragma unroll
            for (int kk = 0; kk < 16; kk += 4) {
                float4 x0 = in[kk],   x1 = in[kk+1], x2 = in[kk+2], x3 = in[kk+3];
                a0 += wv[kk  ].x*x0.x + wv[kk  ].y*x0.y + wv[kk  ].z*x0.z + wv[kk  ].w*x0.w;
                a1 += wv[kk+1].x*x1.x + wv[kk+1].y*x1.y + wv[kk+1].z*x1.z + wv[kk+1].w*x1.w;
                a2 += wv[kk+2].x*x2.x + wv[kk+2].y*x2.y + wv[kk+2].z*x2.z + wv[kk+2].w*x2.w;
                a3 += wv[kk+3].x*x3.x + wv[kk+3].y*x3.y + wv[kk+3].z*x3.z + wv[kk+3].w*x3.w;
            }
            float r = lrelu((a0 + a1) + (a2 + a3));
            T[path*64 + i] = r;
            __syncthreads();
            float o2 = T[i] + T[64 + i];
            c = o2;
            if (path == 0)
                g_x[(b*LL + st)*DD + i] = o2 * 8.0f + pemb[st*DD + i];
        }
        __threadfence();
        __syncthreads();
        if (t == 0) g_flagS[b] = 1;
        return;
    }

    // =================== role: qkv (blocks 8..407) ===================
    if (blk < 8 + BL) {
        const int bl = blk - 8;
        const int b = bl / LL;
        float* xs = sm.qkv.xs;
        float* Qs = sm.qkv.Qs;
        float* mv = sm.qkv.mv;

        if (t == 0) { while (g_flagS[b] == 0) __nanosleep(64); }
        __syncthreads();
        __threadfence();

        if (t < DD) xs[t] = g_x[bl*DD + t];
        __syncthreads();
        if (t < 32) {
            float s = xs[t] + xs[t + 32];
            #pragma unroll
            for (int o = 16; o; o >>= 1) s += __shfl_xor_sync(0xffffffffu, s, o);
            float mean = s * (1.f/64.f);
            float d0 = xs[t] - mean, d1 = xs[t+32] - mean;
            float vs = d0*d0 + d1*d1;
            #pragma unroll
            for (int o = 16; o; o >>= 1) vs += __shfl_xor_sync(0xffffffffu, vs, o);
            if (t == 0) { mv[0] = mean; mv[1] = rsqrtf(vs * (1.f/64.f) + 1e-8f); }
        }
        __syncthreads();
        if (t < DD) {
            float q = (xs[t] - mv[0]) * mv[1] * lnas[t] + lnab[t];   // bb = 0
            Qs[t] = q;
            g_Q[bl*DD + t] = q;
        }
        __syncthreads();

        for (int o = t; o < 3*DD; o += 128) {
            const float* src = (o < DD) ? Qs : xs;
            const float4* w4 = (const float4*)(ipw + (long)o * DD);  // bb = 0
            const float4* s4 = (const float4*)src;
            float acc = 0.f;
            #pragma unroll
            for (int kk = 0; kk < 16; kk++) {
                float4 w = w4[kk], x = s4[kk];
                acc += w.x*x.x + w.y*x.y + w.z*x.z + w.w*x.w;
            }
            acc += ipb[o];
            if      (o < DD)   g_q[bl*DD + o      ] = acc;
            else if (o < 2*DD) g_k[bl*DD + o - 64 ] = acc;
            else               g_v[bl*DD + o - 128] = acc;
        }
        __threadfence();
        __syncthreads();
        if (t == 0) g_flagQ[bl] = 1;
        return;
    }

    // =================== role: kam (blocks 408..1207) ===================
    const int first = (blk < 8 + 2*BL);
    const int bl = first ? (blk - 8 - BL) : (blk - 8 - 2*BL);
    const int bb = first ? 0 : 1;
    const int b = bl / LL, l = bl % LL;
    const int i = t & 63, half = t >> 6;
    const int w = t >> 5, lane = t & 31;
    KamSM& K = sm.kam;

    const float* gq = first ? g_q : g_q2;
    const float* gk = first ? g_k : g_k2;
    const float* gv = first ? g_v : g_v2;

    // wait for q/k/v producer rows 0..l
    if (t == 0) {
        volatile int* flg = first ? g_flagQ : g_flag2;
        for (int r2 = 0; r2 <= l; r2++)
            while (flg[b*LL + r2] == 0) __nanosleep(64);
    }
    __syncthreads();
    __threadfence();

    // load K/V rows <= l (causal prefix), both heads + own q row
    for (int idx = t; idx < (l+1)*DD; idx += 128) {
        int kl = idx >> 6, z = idx & 63;
        int h = z >> 5, d = z & 31;
        int src = (b*LL + kl)*DD + h*HDD + d;
        K.Kh[h][kl*36 + d] = gk[src];
        K.Vh[h][kl*36 + d] = gv[src];
    }
    if (t < DD) K.qrow[t] = gq[bl*DD + t];
    __syncthreads();

    // scores + softmax: warp 0 = head 0, warp 1 = head 1
    if (w < 2) {
        const int h = w;
        float4 qreg[8];
        const float4* qa = (const float4*)(K.qrow + h*HDD);
        #pragma unroll
        for (int kk = 0; kk < 8; kk++) qreg[kk] = qa[kk];
        const float scl = 0.17677669529663687f;

        int k0 = lane, k1 = lane + 32;
        float s0 = -3.0e38f, s1 = -3.0e38f;
        if (k0 <= l) {
            const float4* ka = (const float4*)(K.Kh[h] + k0*36);
            float a = 0.f;
            #pragma unroll
            for (int kk = 0; kk < 8; kk++) {
                float4 kv = ka[kk];
                a += qreg[kk].x*kv.x + qreg[kk].y*kv.y + qreg[kk].z*kv.z + qreg[kk].w*kv.w;
            }
            s0 = a * scl;
        }
        if (k1 <= l && k1 < LL) {
            const float4* ka = (const float4*)(K.Kh[h] + k1*36);
            float a = 0.f;
            #pragma unroll
            for (int kk = 0; kk < 8; kk++) {
                float4 kv = ka[kk];
                a += qreg[kk].x*kv.x + qreg[kk].y*kv.y + qreg[kk].z*kv.z + qreg[kk].w*kv.w;
            }
            s1 = a * scl;
        }
        float mx = fmaxf(s0, s1);
        #pragma unroll
        for (int o = 16; o; o >>= 1) mx = fmaxf(mx, __shfl_xor_sync(0xffffffffu, mx, o));
        float e0 = (k0 <= l) ? __expf(s0 - mx) : 0.f;
        float e1 = (k1 <= l && k1 < LL) ? __expf(s1 - mx) : 0.f;
        float smv = e0 + e1;
        #pragma unroll
        for (int o = 16; o; o >>= 1) smv += __shfl_xor_sync(0xffffffffu, smv, o);
        float inv = 1.f / smv;
        K.ps[w][k0] = e0 * inv;
        if (k1 < LL) K.ps[w][k1] = e1 * inv;
    }
    __syncthreads();

    if (t < DD) {
        const int h = t >> 5, d = t & 31;
        float acc = 0.f;
        for (int kj = 0; kj <= l; kj++)
            acc += K.ps[h][kj] * K.Vh[h][kj*36 + d];
        K.cs[t] = acc;
    }
    __syncthreads();

    {
        const float4* wr = (const float4*)(opw + ((long)bb*DD + i)*DD) + half*8;
        const float4* uu = (const float4*)K.cs + half*8;
        float a = 0.f;
        #pragma unroll
        for (int kk = 0; kk < 8; kk++) {
            float4 ww = wr[kk], x = uu[kk];
            a += ww.x*x.x + ww.y*x.y + ww.z*x.z + ww.w*x.w;
        }
        K.part[t] = a;
    }
    __syncthreads();
    if (t < DD)
        K.xr[t] = K.part[t] + K.part[t+64] + opb[bb*DD + t] + g_Q[bl*DD + t];
    __syncthreads();

    if (t < 32) {
        float s = K.xr[t] + K.xr[t+32];
        #pragma unroll
        for (int o = 16; o; o >>= 1) s += __shfl_xor_sync(0xffffffffu, s, o);
        float mean = s * (1.f/64.f);
        float d0 = K.xr[t]-mean, d1 = K.xr[t+32]-mean;
        float vs = d0*d0 + d1*d1;
        #pragma unroll
        for (int o = 16; o; o >>= 1) vs += __shfl_xor_sync(0xffffffffu, vs, o);
        if (t == 0) { K.mv[0] = mean; K.mv[1] = rsqrtf(vs*(1.f/64.f) + 1e-8f); }
    }
    __syncthreads();
    if (t < DD)
        K.x2[t] = (K.xr[t] - K.mv[0]) * K.mv[1] * fs[bb*DD + t] + fb[bb*DD + t];
    __syncthreads();

    {
        const float4* wr = (const float4*)(c1w + ((long)bb*DD + i)*DD) + half*8;
        const float4* uu = (const float4*)K.x2 + half*8;
        float a = 0.f;
        #pragma unroll
        for (int kk = 0; kk < 8; kk++) {
            float4 ww = wr[kk], x = uu[kk];
            a += ww.x*x.x + ww.y*x.y + ww.z*x.z + ww.w*x.w;
        }
        K.part[t] = a;
    }
    __syncthreads();
    if (t < DD) {
        float v = K.part[t] + K.part[t+64] + c1b[bb*DD + t];
        K.hdn[t] = v > 0.f ? v : 0.f;
    }
    __syncthreads();

    {
        const float4* wr = (const float4*)(c2w + ((long)bb*DD + i)*DD) + half*8;
        const float4* uu = (const float4*)K.hdn + half*8;
        float a = 0.f;
        #pragma unroll
        for (int kk = 0; kk < 8; kk++) {
            float4 ww = wr[kk], x = uu[kk];
            a += ww.x*x.x + ww.y*x.y + ww.z*x.z + ww.w*x.w;
        }
        K.part[t] = a;
    }
    __syncthreads();
    if (t < DD)
        K.xr[t] = K.x2[t] + K.part[t] + K.part[t+64] + c2b[bb*DD + t];
    __syncthreads();

    if (t < 32) {
        float s = K.xr[t] + K.xr[t+32];
        #pragma unroll
        for (int o = 16; o; o >>= 1) s += __shfl_xor_sync(0xffffffffu, s, o);
        float mean = s * (1.f/64.f);
        float d0 = K.xr[t]-mean, d1 = K.xr[t+32]-mean;
        float vs = d0*d0 + d1*d1;
        #pragma unroll
        for (int o = 16; o; o >>= 1) vs += __shfl_xor_sync(0xffffffffu, vs, o);
        if (t == 0) { K.mv[0] = mean; K.mv[1] = rsqrtf(vs*(1.f/64.f) + 1e-8f); }
    }
    __syncthreads();

    if (first) {
        // next-block LN + qkv into DOUBLE BUFFER, then release flag2
        if (t < DD) {
            float q = (K.xr[t] - K.mv[0]) * K.mv[1] * lnas[DD + t] + lnab[DD + t]; // bb=1
            K.Qs[t] = q;
            g_Q[bl*DD + t] = q;
        }
        __syncthreads();
        for (int o = t; o < 3*DD; o += 128) {
            const float* src = (o < DD) ? K.Qs : K.xr;
            const float4* w4 = (const float4*)(ipw + ((long)3*DD + o) * DD);  // bb=1
            const float4* s4 = (const float4*)src;
            float acc = 0.f;
            #pragma unroll
            for (int kk = 0; kk < 16; kk++) {
                float4 ww = w4[kk], x = s4[kk];
                acc += ww.x*x.x + ww.y*x.y + ww.z*x.z + ww.w*x.w;
            }
            acc += ipb[3*DD + o];
            if      (o < DD)   g_q2[bl*DD + o      ] = acc;
            else if (o < 2*DD) g_k2[bl*DD + o - 64 ] = acc;
            else               g_v2[bl*DD + o - 128] = acc;
        }
        __threadfence();
        __syncthreads();
        if (t == 0) g_flag2[bl] = 1;
        return;
    }

    // final LN + logits
    if (t < DD) {
        float lf = (K.xr[t] - K.mv[0]) * K.mv[1] * lls[t] + llb[t];
        K.part[t]      = lf * E[(long)pos[bl]*DD + t];
        K.part[t + 64] = lf * E[(long)neg[bl]*DD + t];
    }
    __syncthreads();
    if (t < 32) {
        float s = K.part[t] + K.part[t+32];
        #pragma unroll
        for (int o = 16; o; o >>= 1) s += __shfl_xor_sync(0xffffffffu, s, o);
        if (t == 0) out[bl] = s;
    } else if (t < 64) {
        int tn = t - 32;
        float s = K.part[64 + tn] + K.part[96 + tn];
        #pragma unroll
        for (int o = 16; o; o >>= 1) s += __shfl_xor_sync(0xffffffffu, s, o);
        if (tn == 0) out[BL + bl] = s;
    }
}

// ---------------- launch ------------------------------------------------------
extern "C" void kernel_launch(void* const* d_in, const int* in_sizes, int n_in,
                              void* d_out, int out_size)
{
    const float* uemb = (const float*)d_in[0];
    const float* E    = (const float*)d_in[1];
    const float* rel  = (const float*)d_in[2];
    const float* Wt   = (const float*)d_in[3];
    const float* W1   = (const float*)d_in[4];
    const float* W2   = (const float*)d_in[5];
    const float* pemb = (const float*)d_in[6];
    const float* lnas = (const float*)d_in[7];
    const float* lnab = (const float*)d_in[8];
    const float* ipw  = (const float*)d_in[9];
    const float* ipb  = (const float*)d_in[10];
    const float* opw  = (const float*)d_in[11];
    const float* opb  = (const float*)d_in[12];
    const float* fs   = (const float*)d_in[13];
    const float* fb   = (const float*)d_in[14];
    const float* c1w  = (const float*)d_in[15];
    const float* c1b  = (const float*)d_in[16];
    const float* c2w  = (const float*)d_in[17];
    const float* c2b  = (const float*)d_in[18];
    const float* lls  = (const float*)d_in[19];
    const float* llb  = (const float*)d_in[20];
    const int*   user = (const int*)d_in[21];
    const int*   seq  = (const int*)d_in[22];
    const int*   pos  = (const int*)d_in[23];
    const int*   neg  = (const int*)d_in[24];
    const int*   mh   = (const int*)d_in[25];
    const int*   mr   = (const int*)d_in[26];
    const int*   mt   = (const int*)d_in[27];
    float* out = (float*)d_out;

    for (int hop = 0; hop < NHOP; hop++) {
        kv_rip<<<320, 256>>>(rel, E, seq, hop);
        kh_rip<<<BL, 256>>>(E, Wt, mh, mr, mt, seq, hop, hop == NHOP - 1);
    }
    kmega_rip<<<8 + 3*BL, 128>>>(W1, W2, uemb, user, pemb, E, seq,
                                 lnas, lnab, ipw, ipb, opw, opb, fs, fb,
                                 c1w, c1b, c2w, c2b, lls, llb, pos, neg, out);
}

// round 15
// speedup vs baseline: 1.1224x; 1.1224x over previous
#include <cuda_runtime.h>
#include <cuda_bf16.h>
#include <cstdint>

#define BB   8
#define LL   50
#define BL   400
#define MM   32
#define NHOP 2
#define DD   64
#define HH   2
#define HDD  32
#define RR   20
#define NBLK 2

// ---------------- scratch ----------------------------------------------------
__device__ float g_item [BL*DD];
__device__ float g_osum [BL*DD];
__device__ float g_V    [BL*RR*DD];
__device__ float g_x    [BL*DD];
__device__ float g_Q    [BL*DD];
__device__ float g_q    [BL*DD];
__device__ float g_k    [BL*DD];
__device__ float g_v    [BL*DD];
__device__ float g_q2   [BL*DD];
__device__ float g_k2   [BL*DD];
__device__ float g_v2   [BL*DD];

__device__ volatile int g_flagI[BL];
__device__ volatile int g_flagS[BB];

__device__ __forceinline__ float lrelu(float x) { return x > 0.f ? x : 0.01f * x; }

// ---------------- kv hop0: V[bl,r,j] from E[seq]; resets flags ---------------
__global__ __launch_bounds__(256) void kv0_rip(
    const float* __restrict__ rel, const float* __restrict__ E,
    const int* __restrict__ seq)
{
    __shared__ __align__(16) float IT[25*DD];
    const int u = blockIdx.x;
    const int r = u >> 4, c = u & 15;
    const int t = threadIdx.x;
    const int j = t & 63, gg = t >> 6;

    // reset pipeline flags for this replay (this node runs before all users)
    if (t == 0) {
        for (int idx = u; idx < BL; idx += 320) g_flagI[idx] = 0;
        if (u < BB) g_flagS[u] = 0;
    }

    float Rj[64];
    const float* Rr = rel + (long)r*4096 + j;
    #pragma unroll
    for (int i = 0; i < 64; i++) Rj[i] = Rr[i*64];

    const int base = c * 25;
    for (int idx = t; idx < 25*DD; idx += 256) {
        int bl = base + (idx >> 6), d = idx & 63;
        IT[idx] = E[(long)seq[bl]*DD + d];
    }
    __syncthreads();

    for (int l = gg; l < 25; l += 4) {
        const float4* it4 = (const float4*)(IT + l*DD);
        float a0 = 0.f, a1 = 0.f, a2 = 0.f, a3 = 0.f;
        #pragma unroll
        for (int k2 = 0; k2 < 4; k2++) {
            float4 x0 = it4[k2], x1 = it4[k2+4], x2 = it4[k2+8], x3 = it4[k2+12];
            a0 += x0.x*Rj[4*k2   ] + x0.y*Rj[4*k2+1 ] + x0.z*Rj[4*k2+2 ] + x0.w*Rj[4*k2+3 ];
            a1 += x1.x*Rj[4*k2+16] + x1.y*Rj[4*k2+17] + x1.z*Rj[4*k2+18] + x1.w*Rj[4*k2+19];
            a2 += x2.x*Rj[4*k2+32] + x2.y*Rj[4*k2+33] + x2.z*Rj[4*k2+34] + x2.w*Rj[4*k2+35];
            a3 += x3.x*Rj[4*k2+48] + x3.y*Rj[4*k2+49] + x3.z*Rj[4*k2+50] + x3.w*Rj[4*k2+51];
        }
        g_V[((long)(base + l)*RR + r)*DD + j] = (a0 + a1) + (a2 + a3);
    }
}

// ---------------- fused: kh(hop0) blocks 0..399 | kv(hop1) blocks 400..719 ---
__global__ __launch_bounds__(256) void khkv_rip(
    const float* __restrict__ rel, const float* __restrict__ E,
    const float* __restrict__ Wt,
    const int* __restrict__ mh, const int* __restrict__ mr, const int* __restrict__ mt,
    const int* __restrict__ seq)
{
    __shared__ __align__(16) float smem[25*DD];   // kv IT; kh uses prefix slices
    const int t = threadIdx.x;

    if (blockIdx.x < BL) {
        // ---------------- kh hop0 ----------------
        float* sc     = smem;            // 32
        float* pr     = smem + 32;       // 32
        float* u_     = smem + 64;       // 64
        float* item_s = smem + 128;      // 64
        float* part   = smem + 192;      // 256
        const int bl = blockIdx.x;
        const int d = t & 63, quarter = t >> 6;
        const int mbase = (bl*NHOP + 0) * MM;

        if (t < DD)
            item_s[t] = E[(long)seq[bl]*DD + t];

        const int m = t >> 3, e8 = t & 7;
        const int hid = mh[mbase + m], rid = mr[mbase + m];
        const float4* Vv = (const float4*)(g_V + ((long)bl*RR + rid) * DD) + e8*2;
        const float4* Hh = (const float4*)(E + (long)hid * DD) + e8*2;
        float4 va0 = Vv[0], va1 = Vv[1], ha0 = Hh[0], ha1 = Hh[1];

        float treg[8];
        const int* mtb = mt + mbase + quarter*8;
        #pragma unroll
        for (int m2 = 0; m2 < 8; m2++)
            treg[m2] = E[(long)mtb[m2]*DD + d];

        float acc = va0.x*ha0.x + va0.y*ha0.y + va0.z*ha0.z + va0.w*ha0.w
                  + va1.x*ha1.x + va1.y*ha1.y + va1.z*ha1.z + va1.w*ha1.w;
        acc += __shfl_down_sync(0xffffffffu, acc, 4, 8);
        acc += __shfl_down_sync(0xffffffffu, acc, 2, 8);
        acc += __shfl_down_sync(0xffffffffu, acc, 1, 8);
        if (e8 == 0) sc[m] = acc;
        __syncthreads();

        if (t < 32) {
            float v = sc[t];
            float mx = v;
            #pragma unroll
            for (int o = 16; o; o >>= 1) mx = fmaxf(mx, __shfl_xor_sync(0xffffffffu, mx, o));
            float e = __expf(v - mx);
            float s = e;
            #pragma unroll
            for (int o = 16; o; o >>= 1) s += __shfl_xor_sync(0xffffffffu, s, o);
            pr[t] = e / s;
        }
        __syncthreads();

        float od = 0.f;
        #pragma unroll
        for (int m2 = 0; m2 < 8; m2++)
            od += pr[quarter*8 + m2] * treg[m2];
        part[t] = od;
        __syncthreads();
        if (t < DD) {
            float o = part[t] + part[t + 64] + part[t + 128] + part[t + 192];
            g_osum[bl*DD + t] = o;
            u_[t] = o + item_s[t];
        }
        __syncthreads();

        const float4* wr = (const float4*)(Wt + d*DD) + quarter*4;
        const float4* uu = (const float4*)u_ + quarter*4;
        float a = 0.f;
        #pragma unroll
        for (int kk = 0; kk < 4; kk++) {
            float4 w = wr[kk], x = uu[kk];
            a += w.x*x.x + w.y*x.y + w.z*x.z + w.w*x.w;
        }
        part[t] = a;
        __syncthreads();
        if (t < DD)
            g_item[bl*DD + t] = lrelu(part[t] + part[t+64] + part[t+128] + part[t+192]);
        __threadfence();
        __syncthreads();
        if (t == 0) g_flagI[bl] = 1;
        return;
    }

    // ---------------- kv hop1 ----------------
    {
        float* IT = smem;
        const int u = blockIdx.x - BL;
        const int r = u >> 4, c = u & 15;
        const int j = t & 63, gg = t >> 6;

        // prefetch R column while producers run
        float Rj[64];
        const float* Rr = rel + (long)r*4096 + j;
        #pragma unroll
        for (int i = 0; i < 64; i++) Rj[i] = Rr[i*64];

        const int base = c * 25;
        if (t == 0) {
            for (int r2 = 0; r2 < 25; r2++)
                while (g_flagI[base + r2] == 0) __nanosleep(64);
        }
        __syncthreads();
        __threadfence();

        for (int idx = t; idx < 25*DD; idx += 256) {
            int bl = base + (idx >> 6), d = idx & 63;
            IT[idx] = g_item[bl*DD + d];
        }
        __syncthreads();

        for (int l = gg; l < 25; l += 4) {
            const float4* it4 = (const float4*)(IT + l*DD);
            float a0 = 0.f, a1 = 0.f, a2 = 0.f, a3 = 0.f;
            #pragma unroll
            for (int k2 = 0; k2 < 4; k2++) {
                float4 x0 = it4[k2], x1 = it4[k2+4], x2 = it4[k2+8], x3 = it4[k2+12];
                a0 += x0.x*Rj[4*k2   ] + x0.y*Rj[4*k2+1 ] + x0.z*Rj[4*k2+2 ] + x0.w*Rj[4*k2+3 ];
                a1 += x1.x*Rj[4*k2+16] + x1.y*Rj[4*k2+17] + x1.z*Rj[4*k2+18] + x1.w*Rj[4*k2+19];
                a2 += x2.x*Rj[4*k2+32] + x2.y*Rj[4*k2+33] + x2.z*Rj[4*k2+34] + x2.w*Rj[4*k2+35];
                a3 += x3.x*Rj[4*k2+48] + x3.y*Rj[4*k2+49] + x3.z*Rj[4*k2+50] + x3.w*Rj[4*k2+51];
            }
            g_V[((long)(base + l)*RR + r)*DD + j] = (a0 + a1) + (a2 + a3);
        }
    }
}

// ---------------- kh hop1 (last): osum += o, no transform --------------------
__global__ __launch_bounds__(256) void kh1_rip(
    const float* __restrict__ E,
    const int* __restrict__ mh, const int* __restrict__ mr, const int* __restrict__ mt)
{
    __shared__ float sc[MM], pr[MM], part[256];
    const int bl = blockIdx.x, t = threadIdx.x;
    const int d = t & 63, quarter = t >> 6;
    const int mbase = (bl*NHOP + 1) * MM;

    const int m = t >> 3, e8 = t & 7;
    const int hid = mh[mbase + m], rid = mr[mbase + m];
    const float4* Vv = (const float4*)(g_V + ((long)bl*RR + rid) * DD) + e8*2;
    const float4* Hh = (const float4*)(E + (long)hid * DD) + e8*2;
    float4 va0 = Vv[0], va1 = Vv[1], ha0 = Hh[0], ha1 = Hh[1];

    float treg[8];
    const int* mtb = mt + mbase + quarter*8;
    #pragma unroll
    for (int m2 = 0; m2 < 8; m2++)
        treg[m2] = E[(long)mtb[m2]*DD + d];

    float acc = va0.x*ha0.x + va0.y*ha0.y + va0.z*ha0.z + va0.w*ha0.w
              + va1.x*ha1.x + va1.y*ha1.y + va1.z*ha1.z + va1.w*ha1.w;
    acc += __shfl_down_sync(0xffffffffu, acc, 4, 8);
    acc += __shfl_down_sync(0xffffffffu, acc, 2, 8);
    acc += __shfl_down_sync(0xffffffffu, acc, 1, 8);
    if (e8 == 0) sc[m] = acc;
    __syncthreads();

    if (t < 32) {
        float v = sc[t];
        float mx = v;
        #pragma unroll
        for (int o = 16; o; o >>= 1) mx = fmaxf(mx, __shfl_xor_sync(0xffffffffu, mx, o));
        float e = __expf(v - mx);
        float s = e;
        #pragma unroll
        for (int o = 16; o; o >>= 1) s += __shfl_xor_sync(0xffffffffu, s, o);
        pr[t] = e / s;
    }
    __syncthreads();

    float od = 0.f;
    #pragma unroll
    for (int m2 = 0; m2 < 8; m2++)
        od += pr[quarter*8 + m2] * treg[m2];
    part[t] = od;
    __syncthreads();
    if (t < DD)
        g_osum[bl*DD + t] += part[t] + part[t + 64] + part[t + 128] + part[t + 192];
}

// ---------------- fused: scan blocks 0..7 | qkv(bb=0) blocks 8..407 ----------
struct ScanSM { float S[LL*DD]; float AB[128]; float T[128]; };
struct QkvSM  { float xs[DD]; float Qs[DD]; float mv[2]; };
union __align__(16) KsqSM { ScanSM scan; QkvSM qkv; };

__global__ __launch_bounds__(128) void ksq_rip(
    const float* __restrict__ W1, const float* __restrict__ W2,
    const float* __restrict__ uemb, const int* __restrict__ user,
    const float* __restrict__ pemb, const float* __restrict__ E,
    const int* __restrict__ seq,
    const float* __restrict__ lnas, const float* __restrict__ lnab,
    const float* __restrict__ ipw,  const float* __restrict__ ipb)
{
    __shared__ KsqSM sm;
    const int blk = blockIdx.x, t = threadIdx.x;

    if (blk < BB) {
        const int b = blk;
        const int i = t & 63, path = t >> 6;
        float* S  = sm.scan.S;
        float* AB = sm.scan.AB;
        float* T  = sm.scan.T;

        const float* W = path ? W2 : W1;
        const float4* wr = (const float4*)(W + i*DD);
        float4 wv[16];
        #pragma unroll
        for (int kk = 0; kk < 16; kk++) wv[kk] = wr[kk];

        for (int idx = t; idx < LL*DD; idx += 128) {
            int l = idx >> 6, d = idx & 63;
            S[idx] = E[(long)seq[b*LL + l]*DD + d] + g_osum[b*LL*DD + idx];
        }
        float c = uemb[(long)user[b] * DD + i];
        __syncthreads();

        for (int st = 0; st < LL; st++) {
            float sv = S[st*DD + i];
            AB[path*64 + i] = path ? (sv * c) : (sv + c);
            __syncthreads();
            const float4* in = (const float4*)(AB + path*64);
            float a0 = 0.f, a1 = 0.f, a2 = 0.f, a3 = 0.f;
            #pragma unroll
            for (int kk = 0; kk < 16; kk += 4) {
                float4 x0 = in[kk],   x1 = in[kk+1], x2 = in[kk+2], x3 = in[kk+3];
                a0 += wv[kk  ].x*x0.x + wv[kk  ].y*x0.y + wv[kk  ].z*x0.z + wv[kk  ].w*x0.w;
                a1 += wv[kk+1].x*x1.x + wv[kk+1].y*x1.y + wv[kk+1].z*x1.z + wv[kk+1].w*x1.w;
                a2 += wv[kk+2].x*x2.x + wv[kk+2].y*x2.y + wv[kk+2].z*x2.z + wv[kk+2].w*x2.w;
                a3 += wv[kk+3].x*x3.x + wv[kk+3].y*x3.y + wv[kk+3].z*x3.z + wv[kk+3].w*x3.w;
            }
            float r = lrelu((a0 + a1) + (a2 + a3));
            T[path*64 + i] = r;
            __syncthreads();
            float o2 = T[i] + T[64 + i];
            c = o2;
            if (path == 0)
                g_x[(b*LL + st)*DD + i] = o2 * 8.0f + pemb[st*DD + i];
        }
        __threadfence();
        __syncthreads();
        if (t == 0) g_flagS[b] = 1;
        return;
    }

    // qkv role (bb = 0)
    {
        const int bl = blk - BB;
        const int b = bl / LL;
        float* xs = sm.qkv.xs;
        float* Qs = sm.qkv.Qs;
        float* mv = sm.qkv.mv;

        if (t == 0) { while (g_flagS[b] == 0) __nanosleep(64); }
        __syncthreads();
        __threadfence();

        if (t < DD) xs[t] = g_x[bl*DD + t];
        __syncthreads();
        if (t < 32) {
            float s = xs[t] + xs[t + 32];
            #pragma unroll
            for (int o = 16; o; o >>= 1) s += __shfl_xor_sync(0xffffffffu, s, o);
            float mean = s * (1.f/64.f);
            float d0 = xs[t] - mean, d1 = xs[t+32] - mean;
            float vs = d0*d0 + d1*d1;
            #pragma unroll
            for (int o = 16; o; o >>= 1) vs += __shfl_xor_sync(0xffffffffu, vs, o);
            if (t == 0) { mv[0] = mean; mv[1] = rsqrtf(vs * (1.f/64.f) + 1e-8f); }
        }
        __syncthreads();
        if (t < DD) {
            float q = (xs[t] - mv[0]) * mv[1] * lnas[t] + lnab[t];
            Qs[t] = q;
            g_Q[bl*DD + t] = q;
        }
        __syncthreads();

        for (int o = t; o < 3*DD; o += 128) {
            const float* src = (o < DD) ? Qs : xs;
            const float4* w4 = (const float4*)(ipw + (long)o * DD);
            const float4* s4 = (const float4*)src;
            float acc = 0.f;
            #pragma unroll
            for (int kk = 0; kk < 16; kk++) {
                float4 w = w4[kk], x = s4[kk];
                acc += w.x*x.x + w.y*x.y + w.z*x.z + w.w*x.w;
            }
            acc += ipb[o];
            if      (o < DD)   g_q[bl*DD + o      ] = acc;
            else if (o < 2*DD) g_k[bl*DD + o - 64 ] = acc;
            else               g_v[bl*DD + o - 128] = acc;
        }
    }
}

// ---------------- attention + out-proj + LN + FFN + next-qkv/logits ----------
__global__ __launch_bounds__(128) void kam_rip(
    const float* __restrict__ opw, const float* __restrict__ opb,
    const float* __restrict__ fs,  const float* __restrict__ fb,
    const float* __restrict__ c1w, const float* __restrict__ c1b,
    const float* __restrict__ c2w, const float* __restrict__ c2b, int bb,
    int last, const float* __restrict__ E,
    const float* __restrict__ lls, const float* __restrict__ llb,
    const int* __restrict__ pos, const int* __restrict__ neg,
    float* __restrict__ out,
    const float* __restrict__ lnas, const float* __restrict__ lnab,
    const float* __restrict__ ipw,  const float* __restrict__ ipb)
{
    __shared__ float Kh[2][LL*36], Vh[2][LL*36];
    __shared__ float qrow[DD];
    __shared__ float ps[2][52];
    __shared__ float cs[DD], xr[DD], x2[DD], hdn[DD], part[128], Qs[DD];
    __shared__ float mv[2];
    const int bl = blockIdx.x, t = threadIdx.x;
    const int b = bl / LL, l = bl % LL;
    const int i = t & 63, half = t >> 6;
    const int w = t >> 5, lane = t & 31;

    const float* gq = bb == 0 ? g_q : g_q2;
    const float* gk = bb == 0 ? g_k : g_k2;
    const float* gv = bb == 0 ? g_v : g_v2;

    // causal prefix K/V (rows <= l), both heads + own q row
    for (int idx = t; idx < (l+1)*DD; idx += 128) {
        int kl = idx >> 6, z = idx & 63;
        int h = z >> 5, d = z & 31;
        int src = (b*LL + kl)*DD + h*HDD + d;
        Kh[h][kl*36 + d] = gk[src];
        Vh[h][kl*36 + d] = gv[src];
    }
    if (t < DD) qrow[t] = gq[bl*DD + t];
    __syncthreads();

    if (w < 2) {
        const int h = w;
        float4 qreg[8];
        const float4* qa = (const float4*)(qrow + h*HDD);
        #pragma unroll
        for (int kk = 0; kk < 8; kk++) qreg[kk] = qa[kk];
        const float scl = 0.17677669529663687f;

        int k0 = lane, k1 = lane + 32;
        float s0 = -3.0e38f, s1 = -3.0e38f;
        if (k0 <= l) {
            const float4* ka = (const float4*)(Kh[h] + k0*36);
            float a = 0.f;
            #pragma unroll
            for (int kk = 0; kk < 8; kk++) {
                float4 kv = ka[kk];
                a += qreg[kk].x*kv.x + qreg[kk].y*kv.y + qreg[kk].z*kv.z + qreg[kk].w*kv.w;
            }
            s0 = a * scl;
        }
        if (k1 <= l && k1 < LL) {
            const float4* ka = (const float4*)(Kh[h] + k1*36);
            float a = 0.f;
            #pragma unroll
            for (int kk = 0; kk < 8; kk++) {
                float4 kv = ka[kk];
                a += qreg[kk].x*kv.x + qreg[kk].y*kv.y + qreg[kk].z*kv.z + qreg[kk].w*kv.w;
            }
            s1 = a * scl;
        }
        float mx = fmaxf(s0, s1);
        #pragma unroll
        for (int o = 16; o; o >>= 1) mx = fmaxf(mx, __shfl_xor_sync(0xffffffffu, mx, o));
        float e0 = (k0 <= l) ? __expf(s0 - mx) : 0.f;
        float e1 = (k1 <= l && k1 < LL) ? __expf(s1 - mx) : 0.f;
        float sm = e0 + e1;
        #pragma unroll
        for (int o = 16; o; o >>= 1) sm += __shfl_xor_sync(0xffffffffu, sm, o);
        float inv = 1.f / sm;
        ps[w][k0] = e0 * inv;
        if (k1 < LL) ps[w][k1] = e1 * inv;
    }
    __syncthreads();

    if (t < DD) {
        const int h = t >> 5, d = t & 31;
        float acc = 0.f;
        for (int kj = 0; kj <= l; kj++)
            acc += ps[h][kj] * Vh[h][kj*36 + d];
        cs[t] = acc;
    }
    __syncthreads();

    {
        const float4* wr = (const float4*)(opw + ((long)bb*DD + i)*DD) + half*8;
        const float4* uu = (const float4*)cs + half*8;
        float a = 0.f;
        #pragma unroll
        for (int kk = 0; kk < 8; kk++) {
            float4 ww = wr[kk], x = uu[kk];
            a += ww.x*x.x + ww.y*x.y + ww.z*x.z + ww.w*x.w;
        }
        part[t] = a;
    }
    __syncthreads();
    if (t < DD)
        xr[t] = part[t] + part[t+64] + opb[bb*DD + t] + g_Q[bl*DD + t];
    __syncthreads();

    if (t < 32) {
        float s = xr[t] + xr[t+32];
        #pragma unroll
        for (int o = 16; o; o >>= 1) s += __shfl_xor_sync(0xffffffffu, s, o);
        float mean = s * (1.f/64.f);
        float d0 = xr[t]-mean, d1 = xr[t+32]-mean;
        float vs = d0*d0 + d1*d1;
        #pragma unroll
        for (int o = 16; o; o >>= 1) vs += __shfl_xor_sync(0xffffffffu, vs, o);
        if (t == 0) { mv[0] = mean; mv[1] = rsqrtf(vs*(1.f/64.f) + 1e-8f); }
    }
    __syncthreads();
    if (t < DD)
        x2[t] = (xr[t] - mv[0]) * mv[1] * fs[bb*DD + t] + fb[bb*DD + t];
    __syncthreads();

    {
        const float4* wr = (const float4*)(c1w + ((long)bb*DD + i)*DD) + half*8;
        const float4* uu = (const float4*)x2 + half*8;
        float a = 0.f;
        #pragma unroll
        for (int kk = 0; kk < 8; kk++) {
            float4 ww = wr[kk], x = uu[kk];
            a += ww.x*x.x + ww.y*x.y + ww.z*x.z + ww.w*x.w;
        }
        part[t] = a;
    }
    __syncthreads();
    if (t < DD) {
        float v = part[t] + part[t+64] + c1b[bb*DD + t];
        hdn[t] = v > 0.f ? v : 0.f;
    }
    __syncthreads();

    {
        const float4* wr = (const float4*)(c2w + ((long)bb*DD + i)*DD) + half*8;
        const float4* uu = (const float4*)hdn + half*8;
        float a = 0.f;
        #pragma unroll
        for (int kk = 0; kk < 8; kk++) {
            float4 ww = wr[kk], x = uu[kk];
            a += ww.x*x.x + ww.y*x.y + ww.z*x.z + ww.w*x.w;
        }
        part[t] = a;
    }
    __syncthreads();
    if (t < DD)
        xr[t] = x2[t] + part[t] + part[t+64] + c2b[bb*DD + t];
    __syncthreads();

    if (t < 32) {
        float s = xr[t] + xr[t+32];
        #pragma unroll
        for (int o = 16; o; o >>= 1) s += __shfl_xor_sync(0xffffffffu, s, o);
        float mean = s * (1.f/64.f);
        float d0 = xr[t]-mean, d1 = xr[t+32]-mean;
        float vs = d0*d0 + d1*d1;
        #pragma unroll
        for (int o = 16; o; o >>= 1) vs += __shfl_xor_sync(0xffffffffu, vs, o);
        if (t == 0) { mv[0] = mean; mv[1] = rsqrtf(vs*(1.f/64.f) + 1e-8f); }
    }
    __syncthreads();

    if (!last) {
        const int b1 = bb + 1;
        if (t < DD) {
            float q = (xr[t] - mv[0]) * mv[1] * lnas[b1*DD + t] + lnab[b1*DD + t];
            Qs[t] = q;
            g_Q[bl*DD + t] = q;
        }
        __syncthreads();
        for (int o = t; o < 3*DD; o += 128) {
            const float* src = (o < DD) ? Qs : xr;
            const float4* w4 = (const float4*)(ipw + ((long)b1*3*DD + o) * DD);
            const float4* s4 = (const float4*)src;
            float acc = 0.f;
            #pragma unroll
            for (int kk = 0; kk < 16; kk++) {
                float4 ww = w4[kk], x = s4[kk];
                acc += ww.x*x.x + ww.y*x.y + ww.z*x.z + ww.w*x.w;
            }
            acc += ipb[b1*3*DD + o];
            if      (o < DD)   g_q2[bl*DD + o      ] = acc;
            else if (o < 2*DD) g_k2[bl*DD + o - 64 ] = acc;
            else               g_v2[bl*DD + o - 128] = acc;
        }
        return;
    }

    if (t < DD) {
        float lf = (xr[t] - mv[0]) * mv[1] * lls[t] + llb[t];
        part[t]      = lf * E[(long)pos[bl]*DD + t];
        part[t + 64] = lf * E[(long)neg[bl]*DD + t];
    }
    __syncthreads();
    if (t < 32) {
        float s = part[t] + part[t+32];
        #pragma unroll
        for (int o = 16; o; o >>= 1) s += __shfl_xor_sync(0xffffffffu, s, o);
        if (t == 0) out[bl] = s;
    } else if (t < 64) {
        int tn = t - 32;
        float s = part[64 + tn] + part[96 + tn];
        #pragma unroll
        for (int o = 16; o; o >>= 1) s += __shfl_xor_sync(0xffffffffu, s, o);
        if (tn == 0) out[BL + bl] = s;
    }
}

// ---------------- launch ------------------------------------------------------
extern "C" void kernel_launch(void* const* d_in, const int* in_sizes, int n_in,
                              void* d_out, int out_size)
{
    const float* uemb = (const float*)d_in[0];
    const float* E    = (const float*)d_in[1];
    const float* rel  = (const float*)d_in[2];
    const float* Wt   = (const float*)d_in[3];
    const float* W1   = (const float*)d_in[4];
    const float* W2   = (const float*)d_in[5];
    const float* pemb = (const float*)d_in[6];
    const float* lnas = (const float*)d_in[7];
    const float* lnab = (const float*)d_in[8];
    const float* ipw  = (const float*)d_in[9];
    const float* ipb  = (const float*)d_in[10];
    const float* opw  = (const float*)d_in[11];
    const float* opb  = (const float*)d_in[12];
    const float* fs   = (const float*)d_in[13];
    const float* fb   = (const float*)d_in[14];
    const float* c1w  = (const float*)d_in[15];
    const float* c1b  = (const float*)d_in[16];
    const float* c2w  = (const float*)d_in[17];
    const float* c2b  = (const float*)d_in[18];
    const float* lls  = (const float*)d_in[19];
    const float* llb  = (const float*)d_in[20];
    const int*   user = (const int*)d_in[21];
    const int*   seq  = (const int*)d_in[22];
    const int*   pos  = (const int*)d_in[23];
    const int*   neg  = (const int*)d_in[24];
    const int*   mh   = (const int*)d_in[25];
    const int*   mr   = (const int*)d_in[26];
    const int*   mt   = (const int*)d_in[27];
    float* out = (float*)d_out;

    kv0_rip<<<320, 256>>>(rel, E, seq);
    khkv_rip<<<BL + 320, 256>>>(rel, E, Wt, mh, mr, mt, seq);
    kh1_rip<<<BL, 256>>>(E, mh, mr, mt);
    ksq_rip<<<BB + BL, 128>>>(W1, W2, uemb, user, pemb, E, seq,
                              lnas, lnab, ipw, ipb);
    kam_rip<<<BL, 128>>>(opw, opb, fs, fb, c1w, c1b, c2w, c2b, 0, 0,
                         E, lls, llb, pos, neg, out, lnas, lnab, ipw, ipb);
    kam_rip<<<BL, 128>>>(opw, opb, fs, fb, c1w, c1b, c2w, c2b, 1, 1,
                         E, lls, llb, pos, neg, out, lnas, lnab, ipw, ipb);
}